// round 15
// baseline (speedup 1.0000x reference)
#include <cuda_runtime.h>
#include <cuda_fp16.h>
#include <cstdint>

#define BB 8
#define SS 2048
#define DD 128
#define NTH 256                   // 8 warps, 1 CTA/SM
#define NCH 16                    // 128-key chunks
#define OUT_W_OFF ((size_t)BB * SS * DD)

#define RSB 272                   // smem row stride bytes (136 halfs)
#define QLO_D 34816               // Q hi->lo delta (128 rows)
#define KLO_D 34816               // K hi->lo delta (128 rows)
#define VBUFB 34816               // V buffer bytes (128 rows hi)

#define QH_OFF 0                  // Q hi 34816 + lo 34816
#define KB_OFF 69632              // K: 128 rows hi+lo (single buf) 69632
#define VB_OFF 139264             // V: 2 bufs x 34816
#define WV_OFF 208896             // winv[128] floats
#define SMEM_TOTAL 209408

__device__ __half gQh[(size_t)BB * SS * DD];
__device__ __half gQl[(size_t)BB * SS * DD];
__device__ __half gKh[(size_t)BB * SS * DD];
__device__ __half gKl[(size_t)BB * SS * DD];
__device__ __half gVh[(size_t)BB * SS * DD];

// ============================= helpers =====================================
__device__ __forceinline__ uint32_t smem_u32(const void* p) {
    uint32_t a;
    asm("{ .reg .u64 t; cvta.to.shared.u64 t, %1; cvt.u32.u64 %0, t; }" : "=r"(a) : "l"(p));
    return a;
}
__device__ __forceinline__ void cpa16(uint32_t dst, const void* src) {
    asm volatile("cp.async.cg.shared.global [%0], [%1], 16;" :: "r"(dst), "l"(src));
}
#define CPA_COMMIT() asm volatile("cp.async.commit_group;")
#define CPA_WAIT1()  asm volatile("cp.async.wait_group 1;")
#define CPA_WAIT0()  asm volatile("cp.async.wait_group 0;")

__device__ __forceinline__ void ldsm4(uint32_t& r0, uint32_t& r1, uint32_t& r2, uint32_t& r3,
                                      uint32_t a) {
    asm volatile("ldmatrix.sync.aligned.m8n8.x4.shared.b16 {%0,%1,%2,%3}, [%4];"
                 : "=r"(r0), "=r"(r1), "=r"(r2), "=r"(r3) : "r"(a));
}
__device__ __forceinline__ void ldsm4t(uint32_t& r0, uint32_t& r1, uint32_t& r2, uint32_t& r3,
                                       uint32_t a) {
    asm volatile("ldmatrix.sync.aligned.m8n8.x4.trans.shared.b16 {%0,%1,%2,%3}, [%4];"
                 : "=r"(r0), "=r"(r1), "=r"(r2), "=r"(r3) : "r"(a));
}
__device__ __forceinline__ void mma16816(float* c, uint32_t a0, uint32_t a1, uint32_t a2,
                                         uint32_t a3, uint32_t b0, uint32_t b1) {
    asm volatile("mma.sync.aligned.m16n8k16.row.col.f32.f16.f16.f32 "
                 "{%0,%1,%2,%3}, {%4,%5,%6,%7}, {%8,%9}, {%0,%1,%2,%3};"
                 : "+f"(c[0]), "+f"(c[1]), "+f"(c[2]), "+f"(c[3])
                 : "r"(a0), "r"(a1), "r"(a2), "r"(a3), "r"(b0), "r"(b1));
}
__device__ __forceinline__ void split2(float a, float b, uint32_t& hi, uint32_t& lo) {
    __half ha = __float2half_rn(a), hb = __float2half_rn(b);
    __half la = __float2half_rn(a - __half2float(ha));
    __half lb = __float2half_rn(b - __half2float(hb));
    hi = (uint32_t)__half_as_ushort(ha) | ((uint32_t)__half_as_ushort(hb) << 16);
    lo = (uint32_t)__half_as_ushort(la) | ((uint32_t)__half_as_ushort(lb) << 16);
}

// =========================== prep: fp32 -> hi/lo ===========================
__global__ void prep_split(const float* __restrict__ Q, const float* __restrict__ K,
                           const float* __restrict__ V) {
    size_t i = (size_t)blockIdx.x * 256 + threadIdx.x;
    if (blockIdx.y == 0) {
        float x = Q[i];
        __half h = __float2half_rn(x);
        gQh[i] = h;
        gQl[i] = __float2half_rn(x - __half2float(h));
    } else if (blockIdx.y == 1) {
        float x = K[i];
        __half h = __float2half_rn(x);
        gKh[i] = h;
        gKl[i] = __float2half_rn(x - __half2float(h));
    } else {
        gVh[i] = __float2half_rn(V[i]);       // V lo unused (2-term PV)
    }
}

// stage 128-row hi+lo chunk (256 threads)
__device__ __forceinline__ void stage128g(int t, uint32_t dH,
                                          const __half* sH, const __half* sL) {
    #pragma unroll
    for (int i = 0; i < 8; i++) {
        int idx = t + NTH * i;                // 0..2047
        int r = idx >> 4, c = idx & 15;
        uint32_t off = (uint32_t)(r * RSB + c * 16);
        cpa16(dH + off, sH + (size_t)r * DD + c * 8);
        cpa16(dH + KLO_D + off, sL + (size_t)r * DD + c * 8);
    }
}
// stage 128-row hi-only chunk
__device__ __forceinline__ void stage128h(int t, uint32_t dH, const __half* sH) {
    #pragma unroll
    for (int i = 0; i < 8; i++) {
        int idx = t + NTH * i;
        int r = idx >> 4, c = idx & 15;
        cpa16(dH + (uint32_t)(r * RSB + c * 16), sH + (size_t)r * DD + c * 8);
    }
}

// ============================= main kernel =================================
__global__ __launch_bounds__(NTH, 1)
void attn_mma(float* __restrict__ out) {
    extern __shared__ __align__(1024) unsigned char sm[];
    const uint32_t sb = smem_u32(sm);
    const int t = threadIdx.x, lane = t & 31, w = t >> 5;
    const int b = blockIdx.x >> 4, q0 = (blockIdx.x & 15) * 128;

    const size_t rowbase = (size_t)b * SS;
    const __half* qh = gQh + (rowbase + q0) * DD;
    const __half* ql = gQl + (rowbase + q0) * DD;
    const __half* kh = gKh + rowbase * DD;
    const __half* kl = gKl + rowbase * DD;
    const __half* vh = gVh + rowbase * DD;

    const uint32_t qa0 = sb + QH_OFF +
        (uint32_t)((w * 16 + (lane & 7) + ((lane >> 3) & 1) * 8) * RSB + ((lane >> 4) & 1) * 16);
    const uint32_t krowoff =
        (uint32_t)(((lane & 7) + ((lane >> 4) & 1) * 8) * RSB + ((lane >> 3) & 1) * 16);
    const uint32_t vrowoff =
        (uint32_t)(((lane & 7) + ((lane >> 3) & 1) * 8) * RSB + ((lane >> 4) & 1) * 16);
    const int r0q = w * 16 + (lane >> 2);     // thread rows: r0q, r0q+8

    // ---- prologue: Q hi+lo + pre-pass K0 hi (into V region) ----
    #pragma unroll
    for (int i = 0; i < 8; i++) {
        int idx = t + NTH * i;                // 0..2047
        int r = idx >> 4, c = idx & 15;
        uint32_t off = (uint32_t)(r * RSB + c * 16);
        cpa16(sb + QH_OFF + off, qh + (size_t)r * DD + c * 8);
        cpa16(sb + QH_OFF + QLO_D + off, ql + (size_t)r * DD + c * 8);
    }
    stage128h(t, sb + VB_OFF, kh);
    CPA_COMMIT();
    CPA_WAIT0();
    __syncthreads();

    // Q hi fragments live in registers for the whole kernel
    uint32_t qfh[8][4];
    #pragma unroll
    for (int kt = 0; kt < 8; kt++)
        ldsm4(qfh[kt][0], qfh[kt][1], qfh[kt][2], qfh[kt][3], qa0 + kt * 32);

    // ============ pass 1: M~ = rowmax(Qhi Khi^T), 1-term, max only =========
    float mm0 = -3.402823466e38f, mm1 = -3.402823466e38f;
    #pragma unroll 1
    for (int i = 0; i < NCH; i++) {
        if (i + 1 < NCH) {
            stage128h(t, sb + VB_OFF + (uint32_t)((i + 1) & 1) * VBUFB,
                      kh + (size_t)(i + 1) * 128 * DD);
            CPA_COMMIT();
            CPA_WAIT1();
        } else {
            CPA_WAIT0();
        }
        __syncthreads();
        const uint32_t kb = sb + VB_OFF + (uint32_t)(i & 1) * VBUFB;
        float S[16][4];
        #pragma unroll
        for (int r = 0; r < 16; r++) { S[r][0] = 0.f; S[r][1] = 0.f; S[r][2] = 0.f; S[r][3] = 0.f; }
        #pragma unroll
        for (int kt = 0; kt < 8; kt++) {
            #pragma unroll
            for (int ng = 0; ng < 8; ng++) {
                uint32_t ka = kb + (uint32_t)(ng * 16 * RSB) + krowoff + kt * 32;
                uint32_t k0, k1, k2, k3;
                ldsm4(k0, k1, k2, k3, ka);
                mma16816(S[2 * ng], qfh[kt][0], qfh[kt][1], qfh[kt][2], qfh[kt][3], k0, k1);
                mma16816(S[2 * ng + 1], qfh[kt][0], qfh[kt][1], qfh[kt][2], qfh[kt][3], k2, k3);
            }
        }
        #pragma unroll
        for (int nt = 0; nt < 16; nt++) {
            mm0 = fmaxf(mm0, fmaxf(S[nt][0], S[nt][1]));
            mm1 = fmaxf(mm1, fmaxf(S[nt][2], S[nt][3]));
        }
        __syncthreads();
    }
    mm0 = fmaxf(mm0, __shfl_xor_sync(0xffffffffu, mm0, 1));
    mm0 = fmaxf(mm0, __shfl_xor_sync(0xffffffffu, mm0, 2));
    mm1 = fmaxf(mm1, __shfl_xor_sync(0xffffffffu, mm1, 1));
    mm1 = fmaxf(mm1, __shfl_xor_sync(0xffffffffu, mm1, 2));
    const float Ms0 = mm0 + 0.25f;            // safe fixed shift (rows warp-local)
    const float Ms1 = mm1 + 0.25f;

    // ---- pass-2 prologue: K0 hi+lo + V0 (one group) ----
    stage128g(t, sb + KB_OFF, kh, kl);
    stage128h(t, sb + VB_OFF, vh);
    CPA_COMMIT();
    CPA_WAIT0();

    float O[16][4];
    #pragma unroll
    for (int n = 0; n < 16; n++) { O[n][0] = 0.f; O[n][1] = 0.f; O[n][2] = 0.f; O[n][3] = 0.f; }
    float l0 = 0.f, l1 = 0.f;

    float* wrow0 = out + OUT_W_OFF + (rowbase + q0 + r0q) * SS + 2 * (lane & 3);
    float* wrow1 = wrow0 + (size_t)8 * SS;

    // ====== pass 2: 3-term S + fixed-shift exp + raw-U store + 2-term PV ===
    #pragma unroll 1
    for (int j = 0; j < NCH; j++) {
        __syncthreads();                       // K(j)/V(j) ready for all warps

        const uint32_t kb = sb + KB_OFF;
        float S[16][4];
        #pragma unroll
        for (int r = 0; r < 16; r++) { S[r][0] = 0.f; S[r][1] = 0.f; S[r][2] = 0.f; S[r][3] = 0.f; }
        #pragma unroll
        for (int kt = 0; kt < 8; kt++) {
            uint32_t ql0, ql1, ql2, ql3;
            ldsm4(ql0, ql1, ql2, ql3, qa0 + kt * 32 + QLO_D);
            #pragma unroll
            for (int ng = 0; ng < 8; ng++) {
                uint32_t ka = kb + (uint32_t)(ng * 16 * RSB) + krowoff + kt * 32;
                uint32_t k0, k1, k2, k3, m0_, m1_, m2_, m3_;
                ldsm4(k0, k1, k2, k3, ka);
                ldsm4(m0_, m1_, m2_, m3_, ka + KLO_D);
                mma16816(S[2 * ng], qfh[kt][0], qfh[kt][1], qfh[kt][2], qfh[kt][3], k0, k1);
                mma16816(S[2 * ng], ql0, ql1, ql2, ql3, k0, k1);
                mma16816(S[2 * ng], qfh[kt][0], qfh[kt][1], qfh[kt][2], qfh[kt][3], m0_, m1_);
                mma16816(S[2 * ng + 1], qfh[kt][0], qfh[kt][1], qfh[kt][2], qfh[kt][3], k2, k3);
                mma16816(S[2 * ng + 1], ql0, ql1, ql2, ql3, k2, k3);
                mma16816(S[2 * ng + 1], qfh[kt][0], qfh[kt][1], qfh[kt][2], qfh[kt][3], m2_, m3_);
            }
        }
        __syncthreads();                       // all warps done reading K(j)

        if (j + 1 < NCH) {                     // K(j+1) into freed buffer; V(j+1) double-buffered
            stage128g(t, sb + KB_OFF, kh + (size_t)(j + 1) * 128 * DD,
                      kl + (size_t)(j + 1) * 128 * DD);
            stage128h(t, sb + VB_OFF + (uint32_t)((j + 1) & 1) * VBUFB,
                      vh + (size_t)(j + 1) * 128 * DD);
            CPA_COMMIT();
        }

        // U = e^{s - M*}; l; raw-U store (fixup multiplies by 1/l later)
        #pragma unroll
        for (int nt = 0; nt < 16; nt++) {
            S[nt][0] = __expf(S[nt][0] - Ms0);
            S[nt][1] = __expf(S[nt][1] - Ms0);
            S[nt][2] = __expf(S[nt][2] - Ms1);
            S[nt][3] = __expf(S[nt][3] - Ms1);
            l0 += S[nt][0] + S[nt][1];
            l1 += S[nt][2] + S[nt][3];
        }
        #pragma unroll
        for (int nt = 0; nt < 16; nt++) {
            *(float2*)(wrow0 + j * 128 + nt * 8) = make_float2(S[nt][0], S[nt][1]);
            *(float2*)(wrow1 + j * 128 + nt * 8) = make_float2(S[nt][2], S[nt][3]);
        }

        // O += P V (2-term: PhVh + PlVh) on V(j) buffer
        const uint32_t vbH = sb + VB_OFF + (uint32_t)(j & 1) * VBUFB;
        #pragma unroll
        for (int kt = 0; kt < 8; kt++) {
            uint32_t ph0, ph1, ph2, ph3, pl0, pl1, pl2, pl3;
            split2(S[2 * kt][0], S[2 * kt][1], ph0, pl0);
            split2(S[2 * kt][2], S[2 * kt][3], ph1, pl1);
            split2(S[2 * kt + 1][0], S[2 * kt + 1][1], ph2, pl2);
            split2(S[2 * kt + 1][2], S[2 * kt + 1][3], ph3, pl3);
            #pragma unroll
            for (int ng = 0; ng < 8; ng++) {
                uint32_t va = vbH + (uint32_t)(kt * 16 * RSB) + vrowoff + ng * 32;
                uint32_t x0, x1, x2, x3;
                ldsm4t(x0, x1, x2, x3, va);
                mma16816(O[2 * ng], ph0, ph1, ph2, ph3, x0, x1);
                mma16816(O[2 * ng], pl0, pl1, pl2, pl3, x0, x1);
                mma16816(O[2 * ng + 1], ph0, ph1, ph2, ph3, x2, x3);
                mma16816(O[2 * ng + 1], pl0, pl1, pl2, pl3, x2, x3);
            }
        }
        if (j + 1 < NCH) CPA_WAIT0();          // K(j+1)/V(j+1) landed before next iter
    }

    // =========================== epilogue ==================================
    l0 += __shfl_xor_sync(0xffffffffu, l0, 1);
    l0 += __shfl_xor_sync(0xffffffffu, l0, 2);
    l1 += __shfl_xor_sync(0xffffffffu, l1, 1);
    l1 += __shfl_xor_sync(0xffffffffu, l1, 2);
    const float linv0 = 1.0f / l0, linv1 = 1.0f / l1;

    float* wvs = (float*)(sm + WV_OFF);
    if ((lane & 3) == 0) {
        wvs[r0q] = linv0;
        wvs[r0q + 8] = linv1;
    }

    float* orow0 = out + (rowbase + q0 + r0q) * DD + 2 * (lane & 3);
    float* orow1 = orow0 + (size_t)8 * DD;
    #pragma unroll
    for (int nt = 0; nt < 16; nt++) {
        *(float2*)(orow0 + nt * 8) = make_float2(O[nt][0] * linv0, O[nt][1] * linv0);
        *(float2*)(orow1 + nt * 8) = make_float2(O[nt][2] * linv1, O[nt][3] * linv1);
    }
    __syncthreads();

    // ============= W fixup: pure multiply (no exp) =========================
    float4* wbase = (float4*)(out + OUT_W_OFF + (rowbase + q0) * SS);
    #pragma unroll 4
    for (int i = 0; i < 256; i++) {
        int fi = t + NTH * i;                  // 0..65535
        float wv = wvs[fi >> 9];               // 512 float4 per row
        float4 v = wbase[fi];
        v.x *= wv; v.y *= wv; v.z *= wv; v.w *= wv;
        wbase[fi] = v;
    }
}

// ===========================================================================
extern "C" void kernel_launch(void* const* d_in, const int* in_sizes, int n_in,
                              void* d_out, int out_size) {
    const float* Q = (const float*)d_in[0];
    const float* K = (const float*)d_in[1];
    const float* V = (const float*)d_in[2];
    float* out = (float*)d_out;

    cudaFuncSetAttribute(attn_mma, cudaFuncAttributeMaxDynamicSharedMemorySize, SMEM_TOTAL);

    prep_split<<<dim3((BB * SS * DD) / 256, 3), 256>>>(Q, K, V);
    attn_mma<<<BB * (SS / 128), NTH, SMEM_TOTAL>>>(out);
}

// round 16
// speedup vs baseline: 1.1778x; 1.1778x over previous
#include <cuda_runtime.h>
#include <cuda_fp16.h>
#include <cstdint>

#define BB 8
#define SS 2048
#define DD 128
#define NTH 512
#define NCHG 16                   // chunks of 64 keys per group (group owns 1024 keys)
#define OUT_W_OFF ((size_t)BB * SS * DD)

#define RSB 272                   // smem row stride bytes (136 halfs)
#define QLO_D 34816               // Q hi->lo delta
#define KLO_D 17408               // K hi->lo delta (64-row chunks)

#define QH_OFF 0                  // Q hi 34816 + lo 34816
#define GK_OFF 69632              // per group: K hi, K lo, V0 hi, V1 hi (4 x 17408)
#define GRP_B  69632
#define OMRG   69632              // merge buffer (reuses group-0 region post-loop)
#define L_OFF  208896             // m[2][128], l[2][128], winv[128]
#define SMEM_TOTAL 211456

__device__ __half gQh[(size_t)BB * SS * DD];
__device__ __half gQl[(size_t)BB * SS * DD];
__device__ __half gKh[(size_t)BB * SS * DD];
__device__ __half gKl[(size_t)BB * SS * DD];
__device__ __half gVh[(size_t)BB * SS * DD];

// ============================= helpers =====================================
__device__ __forceinline__ uint32_t smem_u32(const void* p) {
    uint32_t a;
    asm("{ .reg .u64 t; cvta.to.shared.u64 t, %1; cvt.u32.u64 %0, t; }" : "=r"(a) : "l"(p));
    return a;
}
__device__ __forceinline__ void cpa16(uint32_t dst, const void* src) {
    asm volatile("cp.async.cg.shared.global [%0], [%1], 16;" :: "r"(dst), "l"(src));
}
#define CPA_COMMIT() asm volatile("cp.async.commit_group;")
#define CPA_WAIT1()  asm volatile("cp.async.wait_group 1;")
#define CPA_WAIT0()  asm volatile("cp.async.wait_group 0;")
#define GBAR(id)     asm volatile("bar.sync %0, 256;" :: "r"(id) : "memory")

__device__ __forceinline__ void ldsm4(uint32_t& r0, uint32_t& r1, uint32_t& r2, uint32_t& r3,
                                      uint32_t a) {
    asm volatile("ldmatrix.sync.aligned.m8n8.x4.shared.b16 {%0,%1,%2,%3}, [%4];"
                 : "=r"(r0), "=r"(r1), "=r"(r2), "=r"(r3) : "r"(a));
}
__device__ __forceinline__ void ldsm4t(uint32_t& r0, uint32_t& r1, uint32_t& r2, uint32_t& r3,
                                       uint32_t a) {
    asm volatile("ldmatrix.sync.aligned.m8n8.x4.trans.shared.b16 {%0,%1,%2,%3}, [%4];"
                 : "=r"(r0), "=r"(r1), "=r"(r2), "=r"(r3) : "r"(a));
}
__device__ __forceinline__ void mma16816(float* c, uint32_t a0, uint32_t a1, uint32_t a2,
                                         uint32_t a3, uint32_t b0, uint32_t b1) {
    asm volatile("mma.sync.aligned.m16n8k16.row.col.f32.f16.f16.f32 "
                 "{%0,%1,%2,%3}, {%4,%5,%6,%7}, {%8,%9}, {%0,%1,%2,%3};"
                 : "+f"(c[0]), "+f"(c[1]), "+f"(c[2]), "+f"(c[3])
                 : "r"(a0), "r"(a1), "r"(a2), "r"(a3), "r"(b0), "r"(b1));
}
__device__ __forceinline__ void split2(float a, float b, uint32_t& hi, uint32_t& lo) {
    __half ha = __float2half_rn(a), hb = __float2half_rn(b);
    __half la = __float2half_rn(a - __half2float(ha));
    __half lb = __float2half_rn(b - __half2float(hb));
    hi = (uint32_t)__half_as_ushort(ha) | ((uint32_t)__half_as_ushort(hb) << 16);
    lo = (uint32_t)__half_as_ushort(la) | ((uint32_t)__half_as_ushort(lb) << 16);
}

// =========================== prep: fp32 -> hi/lo ===========================
__global__ void prep_split(const float* __restrict__ Q, const float* __restrict__ K,
                           const float* __restrict__ V) {
    size_t i = (size_t)blockIdx.x * 256 + threadIdx.x;
    if (blockIdx.y == 0) {
        float x = Q[i];
        __half h = __float2half_rn(x);
        gQh[i] = h;
        gQl[i] = __float2half_rn(x - __half2float(h));
    } else if (blockIdx.y == 1) {
        float x = K[i];
        __half h = __float2half_rn(x);
        gKh[i] = h;
        gKl[i] = __float2half_rn(x - __half2float(h));
    } else {
        gVh[i] = __float2half_rn(V[i]);       // V lo unused (2-term PV)
    }
}

// stage one 64-row hi+lo pair into a group's buffer (group's 256 threads)
__device__ __forceinline__ void stage64g(int tg, uint32_t dH,
                                         const __half* sH, const __half* sL) {
    #pragma unroll
    for (int i = 0; i < 4; i++) {
        int idx = tg + 256 * i;               // 0..1023
        int r = idx >> 4, c = idx & 15;
        uint32_t off = (uint32_t)(r * RSB + c * 16);
        cpa16(dH + off, sH + (size_t)r * DD + c * 8);
        cpa16(dH + KLO_D + off, sL + (size_t)r * DD + c * 8);
    }
}
// stage one 64-row hi-only chunk
__device__ __forceinline__ void stage64h(int tg, uint32_t dH, const __half* sH) {
    #pragma unroll
    for (int i = 0; i < 4; i++) {
        int idx = tg + 256 * i;
        int r = idx >> 4, c = idx & 15;
        cpa16(dH + (uint32_t)(r * RSB + c * 16), sH + (size_t)r * DD + c * 8);
    }
}

// S = Q K^T for this warp's 16 rows x 64 keys (3-term fp16 split)
__device__ __forceinline__ void compute_S(float S[8][4], uint32_t qa0, uint32_t kbH,
                                          uint32_t krowoff) {
    #pragma unroll
    for (int r = 0; r < 8; r++) {
        S[r][0] = 0.f; S[r][1] = 0.f; S[r][2] = 0.f; S[r][3] = 0.f;
    }
    #pragma unroll
    for (int kt = 0; kt < 8; kt++) {
        uint32_t qa = qa0 + kt * 32;
        uint32_t qh0, qh1, qh2, qh3, ql0, ql1, ql2, ql3;
        ldsm4(qh0, qh1, qh2, qh3, qa);
        ldsm4(ql0, ql1, ql2, ql3, qa + QLO_D);
        #pragma unroll
        for (int ng = 0; ng < 4; ng++) {
            uint32_t ka = kbH + (uint32_t)(ng * 16 * RSB) + krowoff + kt * 32;
            uint32_t kh0, kh1, kh2, kh3, kl0, kl1, kl2, kl3;
            ldsm4(kh0, kh1, kh2, kh3, ka);
            ldsm4(kl0, kl1, kl2, kl3, ka + KLO_D);
            mma16816(S[2 * ng], qh0, qh1, qh2, qh3, kh0, kh1);
            mma16816(S[2 * ng], ql0, ql1, ql2, ql3, kh0, kh1);
            mma16816(S[2 * ng], qh0, qh1, qh2, qh3, kl0, kl1);
            mma16816(S[2 * ng + 1], qh0, qh1, qh2, qh3, kh2, kh3);
            mma16816(S[2 * ng + 1], ql0, ql1, ql2, ql3, kh2, kh3);
            mma16816(S[2 * ng + 1], qh0, qh1, qh2, qh3, kl2, kl3);
        }
    }
}

// ============================= main kernel =================================
__global__ __launch_bounds__(NTH, 1)
void attn_mma(float* __restrict__ out) {
    extern __shared__ __align__(1024) unsigned char sm[];
    const uint32_t sb = smem_u32(sm);
    const int t = threadIdx.x, lane = t & 31, w = t >> 5;
    const int g = t >> 8, tg = t & 255, gw = w & 7;
    const int b = blockIdx.x >> 4, q0 = (blockIdx.x & 15) * 128;

    const size_t rowbase = (size_t)b * SS;
    const size_t keyoff = (size_t)g * 1024 * DD;        // this group's first key
    const __half* qh = gQh + (rowbase + q0) * DD;
    const __half* ql = gQl + (rowbase + q0) * DD;
    const __half* kh = gKh + rowbase * DD + keyoff;
    const __half* kl = gKl + rowbase * DD + keyoff;
    const __half* vh = gVh + rowbase * DD + keyoff;

    const uint32_t kbH = sb + GK_OFF + (uint32_t)g * GRP_B;    // K hi (+KLO_D = K lo)
    const uint32_t vb0 = kbH + 2 * KLO_D;                      // V hi buf0 (+KLO_D = buf1)
    const int barid = 1 + g;

    const uint32_t qa0 = sb + QH_OFF +
        (uint32_t)((gw * 16 + (lane & 7) + ((lane >> 3) & 1) * 8) * RSB + ((lane >> 4) & 1) * 16);
    const uint32_t krowoff =
        (uint32_t)(((lane & 7) + ((lane >> 4) & 1) * 8) * RSB + ((lane >> 3) & 1) * 16);
    const uint32_t vrowoff =
        (uint32_t)(((lane & 7) + ((lane >> 3) & 1) * 8) * RSB + ((lane >> 4) & 1) * 16);
    const int r0q = gw * 16 + (lane >> 2);    // thread rows: r0q, r0q+8

    // ---- prologue: Q (all threads) + K0/V0 (per group), then V1 ----
    #pragma unroll
    for (int i = 0; i < 4; i++) {
        int idx = t + NTH * i;                // 0..2047
        int r = idx >> 4, c = idx & 15;
        uint32_t off = (uint32_t)(r * RSB + c * 16);
        cpa16(sb + QH_OFF + off, qh + (size_t)r * DD + c * 8);
        cpa16(sb + QH_OFF + QLO_D + off, ql + (size_t)r * DD + c * 8);
    }
    stage64g(tg, kbH, kh, kl);
    stage64h(tg, vb0, vh);
    CPA_COMMIT();                              // group {Q part, K0, V0}
    stage64h(tg, vb0 + KLO_D, vh + (size_t)64 * DD);
    CPA_COMMIT();                              // group {V1}

    float O[16][4];
    #pragma unroll
    for (int n = 0; n < 16; n++) {
        O[n][0] = 0.f; O[n][1] = 0.f; O[n][2] = 0.f; O[n][3] = 0.f;
    }
    float m0 = -3.402823466e38f, m1 = -3.402823466e38f;
    float l0 = 0.f, l1 = 0.f;

    float* wrow0 = out + OUT_W_OFF + (rowbase + q0 + r0q) * SS + g * 1024 + 2 * (lane & 3);
    float* wrow1 = wrow0 + (size_t)8 * SS;

    // ===================== group-local chunk loop ==========================
    #pragma unroll 1
    for (int j = 0; j < NCHG; j++) {
        if (j < NCHG - 1) CPA_WAIT1();         // K(j), V(j) done; V(j+1) may pend
        else              CPA_WAIT0();
        GBAR(barid);                           // staged data visible to the group

        float S[8][4];
        compute_S(S, qa0, kbH, krowoff);

        GBAR(barid);                           // group done with K(j)
        if (j + 1 < NCHG) {                    // restage K(j+1) under scalar+PV
            stage64g(tg, kbH, kh + (size_t)(j + 1) * 64 * DD,
                     kl + (size_t)(j + 1) * 64 * DD);
            CPA_COMMIT();
        }

        // raw scores to gmem (fixup sweep normalizes later)
        #pragma unroll
        for (int nt = 0; nt < 8; nt++) {
            *(float2*)(wrow0 + j * 64 + nt * 8) = make_float2(S[nt][0], S[nt][1]);
            *(float2*)(wrow1 + j * 64 + nt * 8) = make_float2(S[nt][2], S[nt][3]);
        }

        // online softmax (group-local)
        float cm0 = S[0][0], cm1 = S[0][2];
        #pragma unroll
        for (int nt = 0; nt < 8; nt++) {
            cm0 = fmaxf(cm0, fmaxf(S[nt][0], S[nt][1]));
            cm1 = fmaxf(cm1, fmaxf(S[nt][2], S[nt][3]));
        }
        cm0 = fmaxf(cm0, __shfl_xor_sync(0xffffffffu, cm0, 1));
        cm0 = fmaxf(cm0, __shfl_xor_sync(0xffffffffu, cm0, 2));
        cm1 = fmaxf(cm1, __shfl_xor_sync(0xffffffffu, cm1, 1));
        cm1 = fmaxf(cm1, __shfl_xor_sync(0xffffffffu, cm1, 2));
        float nm0 = fmaxf(m0, cm0), nm1 = fmaxf(m1, cm1);
        float a0 = __expf(m0 - nm0), a1 = __expf(m1 - nm1);
        m0 = nm0; m1 = nm1;
        l0 *= a0; l1 *= a1;
        #pragma unroll
        for (int nt = 0; nt < 8; nt++) {
            S[nt][0] = __expf(S[nt][0] - nm0);
            S[nt][1] = __expf(S[nt][1] - nm0);
            S[nt][2] = __expf(S[nt][2] - nm1);
            S[nt][3] = __expf(S[nt][3] - nm1);
            l0 += S[nt][0] + S[nt][1];
            l1 += S[nt][2] + S[nt][3];
        }
        #pragma unroll
        for (int nt = 0; nt < 16; nt++) {
            O[nt][0] *= a0; O[nt][1] *= a0;
            O[nt][2] *= a1; O[nt][3] *= a1;
        }

        // O += P V (2-term: PhVh + PlVh), V hi only, double-buffered
        const uint32_t vbH = vb0 + (uint32_t)(j & 1) * KLO_D;
        #pragma unroll
        for (int kt = 0; kt < 4; kt++) {
            uint32_t ph0, ph1, ph2, ph3, pl0, pl1, pl2, pl3;
            split2(S[2 * kt][0], S[2 * kt][1], ph0, pl0);
            split2(S[2 * kt][2], S[2 * kt][3], ph1, pl1);
            split2(S[2 * kt + 1][0], S[2 * kt + 1][1], ph2, pl2);
            split2(S[2 * kt + 1][2], S[2 * kt + 1][3], ph3, pl3);
            #pragma unroll
            for (int ng = 0; ng < 8; ng++) {
                uint32_t va = vbH + (uint32_t)(kt * 16 * RSB) + vrowoff + ng * 32;
                uint32_t x0, x1, x2, x3;
                ldsm4t(x0, x1, x2, x3, va);
                mma16816(O[2 * ng], ph0, ph1, ph2, ph3, x0, x1);
                mma16816(O[2 * ng], pl0, pl1, pl2, pl3, x0, x1);
                mma16816(O[2 * ng + 1], ph0, ph1, ph2, ph3, x2, x3);
                mma16816(O[2 * ng + 1], pl0, pl1, pl2, pl3, x2, x3);
            }
        }

        GBAR(barid);                           // group done with V(j)
        if (j + 2 < NCHG) {                    // V(j+2) into freed buffer (j&1)
            stage64h(tg, vb0 + (uint32_t)(j & 1) * KLO_D,
                     vh + (size_t)(j + 2) * 64 * DD);
            CPA_COMMIT();
        }
    }

    // ======================== merge epilogue ===============================
    l0 += __shfl_xor_sync(0xffffffffu, l0, 1);
    l0 += __shfl_xor_sync(0xffffffffu, l0, 2);
    l1 += __shfl_xor_sync(0xffffffffu, l1, 1);
    l1 += __shfl_xor_sync(0xffffffffu, l1, 2);

    float* msm = (float*)(sm + L_OFF);         // [2][128]
    float* lsm = (float*)(sm + L_OFF + 1024);  // [2][128]
    float* wvs = (float*)(sm + L_OFF + 2048);  // winv[128]
    if ((lane & 3) == 0) {
        msm[g * 128 + r0q]     = m0;  msm[g * 128 + r0q + 8] = m1;
        lsm[g * 128 + r0q]     = l0;  lsm[g * 128 + r0q + 8] = l1;
    }
    __syncthreads();

    float MA0 = msm[r0q],       MB0 = msm[128 + r0q];
    float MA1 = msm[r0q + 8],   MB1 = msm[128 + r0q + 8];
    float M0 = fmaxf(MA0, MB0), M1 = fmaxf(MA1, MB1);
    float lt0 = __expf(MA0 - M0) * lsm[r0q]     + __expf(MB0 - M0) * lsm[128 + r0q];
    float lt1 = __expf(MA1 - M1) * lsm[r0q + 8] + __expf(MB1 - M1) * lsm[128 + r0q + 8];
    float sc0 = __expf(m0 - M0) / lt0;         // scale for this thread's own partial
    float sc1 = __expf(m1 - M1) / lt1;
    if (g == 0 && (lane & 3) == 0) {
        wvs[r0q]     = __expf(-M0) / lt0;
        wvs[r0q + 8] = __expf(-M1) / lt1;
    }

    float* ob = (float*)(sm + OMRG);           // [128][128]
    if (g == 1) {
        #pragma unroll
        for (int nt = 0; nt < 16; nt++) {
            int col = nt * 8 + (lane & 3) * 2;
            *(float2*)(ob + r0q * 128 + col) =
                make_float2(O[nt][0] * sc0, O[nt][1] * sc0);
            *(float2*)(ob + (r0q + 8) * 128 + col) =
                make_float2(O[nt][2] * sc1, O[nt][3] * sc1);
        }
    }
    __syncthreads();

    if (g == 0) {
        float* orow0 = out + (rowbase + q0 + r0q) * DD + 2 * (lane & 3);
        float* orow1 = orow0 + (size_t)8 * DD;
        #pragma unroll
        for (int nt = 0; nt < 16; nt++) {
            int col = nt * 8 + (lane & 3) * 2;
            float2 pb0 = *(float2*)(ob + r0q * 128 + col);
            float2 pb1 = *(float2*)(ob + (r0q + 8) * 128 + col);
            *(float2*)(orow0 + nt * 8) =
                make_float2(O[nt][0] * sc0 + pb0.x, O[nt][1] * sc0 + pb0.y);
            *(float2*)(orow1 + nt * 8) =
                make_float2(O[nt][2] * sc1 + pb1.x, O[nt][3] * sc1 + pb1.y);
        }
    }
    __syncthreads();

    // ======================= W fixup sweep (this CTA) ======================
    float4* wbase = (float4*)(out + OUT_W_OFF + (rowbase + q0) * SS);
    #pragma unroll 4
    for (int i = 0; i < 128; i++) {
        int fi = t + NTH * i;                  // 0..65535
        float wv = wvs[fi >> 9];               // 512 float4 per row
        float4 v = wbase[fi];
        v.x = __expf(v.x) * wv;
        v.y = __expf(v.y) * wv;
        v.z = __expf(v.z) * wv;
        v.w = __expf(v.w) * wv;
        wbase[fi] = v;
    }
}

// ===========================================================================
extern "C" void kernel_launch(void* const* d_in, const int* in_sizes, int n_in,
                              void* d_out, int out_size) {
    const float* Q = (const float*)d_in[0];
    const float* K = (const float*)d_in[1];
    const float* V = (const float*)d_in[2];
    float* out = (float*)d_out;

    cudaFuncSetAttribute(attn_mma, cudaFuncAttributeMaxDynamicSharedMemorySize, SMEM_TOTAL);

    prep_split<<<dim3((BB * SS * DD) / 256, 3), 256>>>(Q, K, V);
    attn_mma<<<BB * (SS / 128), NTH, SMEM_TOTAL>>>(out);
}

// round 17
// speedup vs baseline: 1.3156x; 1.1170x over previous
#include <cuda_runtime.h>
#include <cuda_fp16.h>
#include <cstdint>

#define BB 8
#define SS 2048
#define DD 128
#define NTH 512
#define NCHG 16                   // chunks of 64 keys per group (group owns 1024 keys)
#define OUT_W_OFF ((size_t)BB * SS * DD)

#define RSB 272                   // smem row stride bytes (136 halfs)
#define QLO_D 34816               // Q hi->lo delta
#define KLO_D 17408               // K hi->lo delta (64-row chunks)

#define QH_OFF 0                  // Q hi 34816 + lo 34816
#define GK_OFF 69632              // per group: K hi, K lo, V0 hi, V1 hi (4 x 17408)
#define GRP_B  69632
#define OMRG   69632              // merge buffer (reuses group-0 region post-loop)
#define L_OFF  208896             // m[2][128], l[2][128], winv[128]
#define SMEM_TOTAL 211456

__device__ __half gQh[(size_t)BB * SS * DD];
__device__ __half gQl[(size_t)BB * SS * DD];
__device__ __half gKh[(size_t)BB * SS * DD];
__device__ __half gKl[(size_t)BB * SS * DD];
__device__ __half gVh[(size_t)BB * SS * DD];

// ============================= helpers =====================================
__device__ __forceinline__ uint32_t smem_u32(const void* p) {
    uint32_t a;
    asm("{ .reg .u64 t; cvta.to.shared.u64 t, %1; cvt.u32.u64 %0, t; }" : "=r"(a) : "l"(p));
    return a;
}
__device__ __forceinline__ void cpa16(uint32_t dst, const void* src) {
    asm volatile("cp.async.cg.shared.global [%0], [%1], 16;" :: "r"(dst), "l"(src));
}
#define CPA_COMMIT() asm volatile("cp.async.commit_group;")
#define CPA_WAIT1()  asm volatile("cp.async.wait_group 1;")
#define CPA_WAIT0()  asm volatile("cp.async.wait_group 0;")
#define GBAR(id)     asm volatile("bar.sync %0, 256;" :: "r"(id) : "memory")

__device__ __forceinline__ void ldsm4(uint32_t& r0, uint32_t& r1, uint32_t& r2, uint32_t& r3,
                                      uint32_t a) {
    asm volatile("ldmatrix.sync.aligned.m8n8.x4.shared.b16 {%0,%1,%2,%3}, [%4];"
                 : "=r"(r0), "=r"(r1), "=r"(r2), "=r"(r3) : "r"(a));
}
__device__ __forceinline__ void ldsm4t(uint32_t& r0, uint32_t& r1, uint32_t& r2, uint32_t& r3,
                                       uint32_t a) {
    asm volatile("ldmatrix.sync.aligned.m8n8.x4.trans.shared.b16 {%0,%1,%2,%3}, [%4];"
                 : "=r"(r0), "=r"(r1), "=r"(r2), "=r"(r3) : "r"(a));
}
__device__ __forceinline__ void mma16816(float* c, uint32_t a0, uint32_t a1, uint32_t a2,
                                         uint32_t a3, uint32_t b0, uint32_t b1) {
    asm volatile("mma.sync.aligned.m16n8k16.row.col.f32.f16.f16.f32 "
                 "{%0,%1,%2,%3}, {%4,%5,%6,%7}, {%8,%9}, {%0,%1,%2,%3};"
                 : "+f"(c[0]), "+f"(c[1]), "+f"(c[2]), "+f"(c[3])
                 : "r"(a0), "r"(a1), "r"(a2), "r"(a3), "r"(b0), "r"(b1));
}
// pack {lo=a, hi=b} into one fp16x2 register (single cvt instruction)
__device__ __forceinline__ uint32_t pack2h(float a, float b) {
    uint32_t r;
    asm("cvt.rn.f16x2.f32 %0, %1, %2;" : "=r"(r) : "f"(b), "f"(a));
    return r;
}

// =========================== prep: fp32 -> hi/lo ===========================
__global__ void prep_split(const float* __restrict__ Q, const float* __restrict__ K,
                           const float* __restrict__ V) {
    size_t i = (size_t)blockIdx.x * 256 + threadIdx.x;
    if (blockIdx.y == 0) {
        float x = Q[i];
        __half h = __float2half_rn(x);
        gQh[i] = h;
        gQl[i] = __float2half_rn(x - __half2float(h));
    } else if (blockIdx.y == 1) {
        float x = K[i];
        __half h = __float2half_rn(x);
        gKh[i] = h;
        gKl[i] = __float2half_rn(x - __half2float(h));
    } else {
        gVh[i] = __float2half_rn(V[i]);       // V lo unused (1-term PV)
    }
}

// stage one 64-row hi+lo pair into a group's buffer (group's 256 threads)
__device__ __forceinline__ void stage64g(int tg, uint32_t dH,
                                         const __half* sH, const __half* sL) {
    #pragma unroll
    for (int i = 0; i < 4; i++) {
        int idx = tg + 256 * i;               // 0..1023
        int r = idx >> 4, c = idx & 15;
        uint32_t off = (uint32_t)(r * RSB + c * 16);
        cpa16(dH + off, sH + (size_t)r * DD + c * 8);
        cpa16(dH + KLO_D + off, sL + (size_t)r * DD + c * 8);
    }
}
// stage one 64-row hi-only chunk
__device__ __forceinline__ void stage64h(int tg, uint32_t dH, const __half* sH) {
    #pragma unroll
    for (int i = 0; i < 4; i++) {
        int idx = tg + 256 * i;
        int r = idx >> 4, c = idx & 15;
        cpa16(dH + (uint32_t)(r * RSB + c * 16), sH + (size_t)r * DD + c * 8);
    }
}

// S = Q K^T for this warp's 16 rows x 64 keys (3-term fp16 split)
__device__ __forceinline__ void compute_S(float S[8][4], uint32_t qa0, uint32_t kbH,
                                          uint32_t krowoff) {
    #pragma unroll
    for (int r = 0; r < 8; r++) {
        S[r][0] = 0.f; S[r][1] = 0.f; S[r][2] = 0.f; S[r][3] = 0.f;
    }
    #pragma unroll
    for (int kt = 0; kt < 8; kt++) {
        uint32_t qa = qa0 + kt * 32;
        uint32_t qh0, qh1, qh2, qh3, ql0, ql1, ql2, ql3;
        ldsm4(qh0, qh1, qh2, qh3, qa);
        ldsm4(ql0, ql1, ql2, ql3, qa + QLO_D);
        #pragma unroll
        for (int ng = 0; ng < 4; ng++) {
            uint32_t ka = kbH + (uint32_t)(ng * 16 * RSB) + krowoff + kt * 32;
            uint32_t kh0, kh1, kh2, kh3, kl0, kl1, kl2, kl3;
            ldsm4(kh0, kh1, kh2, kh3, ka);
            ldsm4(kl0, kl1, kl2, kl3, ka + KLO_D);
            mma16816(S[2 * ng], qh0, qh1, qh2, qh3, kh0, kh1);
            mma16816(S[2 * ng], ql0, ql1, ql2, ql3, kh0, kh1);
            mma16816(S[2 * ng], qh0, qh1, qh2, qh3, kl0, kl1);
            mma16816(S[2 * ng + 1], qh0, qh1, qh2, qh3, kh2, kh3);
            mma16816(S[2 * ng + 1], ql0, ql1, ql2, ql3, kh2, kh3);
            mma16816(S[2 * ng + 1], qh0, qh1, qh2, qh3, kl2, kl3);
        }
    }
}

// ============================= main kernel =================================
__global__ __launch_bounds__(NTH, 1)
void attn_mma(float* __restrict__ out) {
    extern __shared__ __align__(1024) unsigned char sm[];
    const uint32_t sb = smem_u32(sm);
    const int t = threadIdx.x, lane = t & 31, w = t >> 5;
    const int g = t >> 8, tg = t & 255, gw = w & 7;
    const int b = blockIdx.x >> 4, q0 = (blockIdx.x & 15) * 128;

    const size_t rowbase = (size_t)b * SS;
    const size_t keyoff = (size_t)g * 1024 * DD;        // this group's first key
    const __half* qh = gQh + (rowbase + q0) * DD;
    const __half* ql = gQl + (rowbase + q0) * DD;
    const __half* kh = gKh + rowbase * DD + keyoff;
    const __half* kl = gKl + rowbase * DD + keyoff;
    const __half* vh = gVh + rowbase * DD + keyoff;

    const uint32_t kbH = sb + GK_OFF + (uint32_t)g * GRP_B;    // K hi (+KLO_D = K lo)
    const uint32_t vb0 = kbH + 2 * KLO_D;                      // V hi buf0 (+KLO_D = buf1)
    const int barid = 1 + g;

    const uint32_t qa0 = sb + QH_OFF +
        (uint32_t)((gw * 16 + (lane & 7) + ((lane >> 3) & 1) * 8) * RSB + ((lane >> 4) & 1) * 16);
    const uint32_t krowoff =
        (uint32_t)(((lane & 7) + ((lane >> 4) & 1) * 8) * RSB + ((lane >> 3) & 1) * 16);
    const uint32_t vrowoff =
        (uint32_t)(((lane & 7) + ((lane >> 3) & 1) * 8) * RSB + ((lane >> 4) & 1) * 16);
    const int r0q = gw * 16 + (lane >> 2);    // thread rows: r0q, r0q+8

    // ---- prologue: Q (all threads) + K0/V0 (per group), then V1 ----
    #pragma unroll
    for (int i = 0; i < 4; i++) {
        int idx = t + NTH * i;                // 0..2047
        int r = idx >> 4, c = idx & 15;
        uint32_t off = (uint32_t)(r * RSB + c * 16);
        cpa16(sb + QH_OFF + off, qh + (size_t)r * DD + c * 8);
        cpa16(sb + QH_OFF + QLO_D + off, ql + (size_t)r * DD + c * 8);
    }
    stage64g(tg, kbH, kh, kl);
    stage64h(tg, vb0, vh);
    CPA_COMMIT();                              // group {Q part, K0, V0}
    stage64h(tg, vb0 + KLO_D, vh + (size_t)64 * DD);
    CPA_COMMIT();                              // group {V1}

    float O[16][4];
    #pragma unroll
    for (int n = 0; n < 16; n++) {
        O[n][0] = 0.f; O[n][1] = 0.f; O[n][2] = 0.f; O[n][3] = 0.f;
    }
    float m0 = -3.402823466e38f, m1 = -3.402823466e38f;
    float l0 = 0.f, l1 = 0.f;

    float* wrow0 = out + OUT_W_OFF + (rowbase + q0 + r0q) * SS + g * 1024 + 2 * (lane & 3);
    float* wrow1 = wrow0 + (size_t)8 * SS;

    // ===================== group-local chunk loop ==========================
    #pragma unroll 1
    for (int j = 0; j < NCHG; j++) {
        if (j < NCHG - 1) CPA_WAIT1();         // K(j), V(j) done; V(j+1) may pend
        else              CPA_WAIT0();
        GBAR(barid);                           // staged data visible to the group

        float S[8][4];
        compute_S(S, qa0, kbH, krowoff);

        GBAR(barid);                           // group done with K(j)
        if (j + 1 < NCHG) {                    // restage K(j+1) under scalar+PV
            stage64g(tg, kbH, kh + (size_t)(j + 1) * 64 * DD,
                     kl + (size_t)(j + 1) * 64 * DD);
            CPA_COMMIT();
        }

        // raw scores to gmem (fixup sweep normalizes later)
        #pragma unroll
        for (int nt = 0; nt < 8; nt++) {
            *(float2*)(wrow0 + j * 64 + nt * 8) = make_float2(S[nt][0], S[nt][1]);
            *(float2*)(wrow1 + j * 64 + nt * 8) = make_float2(S[nt][2], S[nt][3]);
        }

        // online softmax (group-local)
        float cm0 = S[0][0], cm1 = S[0][2];
        #pragma unroll
        for (int nt = 0; nt < 8; nt++) {
            cm0 = fmaxf(cm0, fmaxf(S[nt][0], S[nt][1]));
            cm1 = fmaxf(cm1, fmaxf(S[nt][2], S[nt][3]));
        }
        cm0 = fmaxf(cm0, __shfl_xor_sync(0xffffffffu, cm0, 1));
        cm0 = fmaxf(cm0, __shfl_xor_sync(0xffffffffu, cm0, 2));
        cm1 = fmaxf(cm1, __shfl_xor_sync(0xffffffffu, cm1, 1));
        cm1 = fmaxf(cm1, __shfl_xor_sync(0xffffffffu, cm1, 2));
        float nm0 = fmaxf(m0, cm0), nm1 = fmaxf(m1, cm1);
        float a0 = __expf(m0 - nm0), a1 = __expf(m1 - nm1);
        m0 = nm0; m1 = nm1;
        l0 *= a0; l1 *= a1;
        #pragma unroll
        for (int nt = 0; nt < 8; nt++) {
            S[nt][0] = __expf(S[nt][0] - nm0);
            S[nt][1] = __expf(S[nt][1] - nm0);
            S[nt][2] = __expf(S[nt][2] - nm1);
            S[nt][3] = __expf(S[nt][3] - nm1);
            l0 += S[nt][0] + S[nt][1];
            l1 += S[nt][2] + S[nt][3];
        }
        // O rescale — skipped once the running max is stable for the warp
        if (__any_sync(0xffffffffu, (a0 != 1.0f) | (a1 != 1.0f))) {
            #pragma unroll
            for (int nt = 0; nt < 16; nt++) {
                O[nt][0] *= a0; O[nt][1] *= a0;
                O[nt][2] *= a1; O[nt][3] *= a1;
            }
        }

        // pack P fragments (fp16, single precision term) — S dies here
        uint32_t PH[16];
        #pragma unroll
        for (int kt = 0; kt < 4; kt++) {
            PH[4 * kt]     = pack2h(S[2 * kt][0], S[2 * kt][1]);
            PH[4 * kt + 1] = pack2h(S[2 * kt][2], S[2 * kt][3]);
            PH[4 * kt + 2] = pack2h(S[2 * kt + 1][0], S[2 * kt + 1][1]);
            PH[4 * kt + 3] = pack2h(S[2 * kt + 1][2], S[2 * kt + 1][3]);
        }

        // O += P V (1-term: Ph Vh), V double-buffered
        const uint32_t vbH = vb0 + (uint32_t)(j & 1) * KLO_D;
        #pragma unroll
        for (int kt = 0; kt < 4; kt++) {
            #pragma unroll
            for (int ng = 0; ng < 8; ng++) {
                uint32_t va = vbH + (uint32_t)(kt * 16 * RSB) + vrowoff + ng * 32;
                uint32_t x0, x1, x2, x3;
                ldsm4t(x0, x1, x2, x3, va);
                mma16816(O[2 * ng], PH[4 * kt], PH[4 * kt + 1], PH[4 * kt + 2], PH[4 * kt + 3], x0, x1);
                mma16816(O[2 * ng + 1], PH[4 * kt], PH[4 * kt + 1], PH[4 * kt + 2], PH[4 * kt + 3], x2, x3);
            }
        }

        GBAR(barid);                           // group done with V(j)
        if (j + 2 < NCHG) {                    // V(j+2) into freed buffer (j&1)
            stage64h(tg, vb0 + (uint32_t)(j & 1) * KLO_D,
                     vh + (size_t)(j + 2) * 64 * DD);
            CPA_COMMIT();
        }
    }

    // ======================== merge epilogue ===============================
    l0 += __shfl_xor_sync(0xffffffffu, l0, 1);
    l0 += __shfl_xor_sync(0xffffffffu, l0, 2);
    l1 += __shfl_xor_sync(0xffffffffu, l1, 1);
    l1 += __shfl_xor_sync(0xffffffffu, l1, 2);

    float* msm = (float*)(sm + L_OFF);         // [2][128]
    float* lsm = (float*)(sm + L_OFF + 1024);  // [2][128]
    float* wvs = (float*)(sm + L_OFF + 2048);  // winv[128]
    if ((lane & 3) == 0) {
        msm[g * 128 + r0q]     = m0;  msm[g * 128 + r0q + 8] = m1;
        lsm[g * 128 + r0q]     = l0;  lsm[g * 128 + r0q + 8] = l1;
    }
    __syncthreads();

    float MA0 = msm[r0q],       MB0 = msm[128 + r0q];
    float MA1 = msm[r0q + 8],   MB1 = msm[128 + r0q + 8];
    float M0 = fmaxf(MA0, MB0), M1 = fmaxf(MA1, MB1);
    float lt0 = __expf(MA0 - M0) * lsm[r0q]     + __expf(MB0 - M0) * lsm[128 + r0q];
    float lt1 = __expf(MA1 - M1) * lsm[r0q + 8] + __expf(MB1 - M1) * lsm[128 + r0q + 8];
    float sc0 = __expf(m0 - M0) / lt0;         // scale for this thread's own partial
    float sc1 = __expf(m1 - M1) / lt1;
    if (g == 0 && (lane & 3) == 0) {
        wvs[r0q]     = __expf(-M0) / lt0;
        wvs[r0q + 8] = __expf(-M1) / lt1;
    }

    float* ob = (float*)(sm + OMRG);           // [128][128]
    if (g == 1) {
        #pragma unroll
        for (int nt = 0; nt < 16; nt++) {
            int col = nt * 8 + (lane & 3) * 2;
            *(float2*)(ob + r0q * 128 + col) =
                make_float2(O[nt][0] * sc0, O[nt][1] * sc0);
            *(float2*)(ob + (r0q + 8) * 128 + col) =
                make_float2(O[nt][2] * sc1, O[nt][3] * sc1);
        }
    }
    __syncthreads();

    if (g == 0) {
        float* orow0 = out + (rowbase + q0 + r0q) * DD + 2 * (lane & 3);
        float* orow1 = orow0 + (size_t)8 * DD;
        #pragma unroll
        for (int nt = 0; nt < 16; nt++) {
            int col = nt * 8 + (lane & 3) * 2;
            float2 pb0 = *(float2*)(ob + r0q * 128 + col);
            float2 pb1 = *(float2*)(ob + (r0q + 8) * 128 + col);
            *(float2*)(orow0 + nt * 8) =
                make_float2(O[nt][0] * sc0 + pb0.x, O[nt][1] * sc0 + pb0.y);
            *(float2*)(orow1 + nt * 8) =
                make_float2(O[nt][2] * sc1 + pb1.x, O[nt][3] * sc1 + pb1.y);
        }
    }
    __syncthreads();

    // ======================= W fixup sweep (this CTA) ======================
    float4* wbase = (float4*)(out + OUT_W_OFF + (rowbase + q0) * SS);
    #pragma unroll 4
    for (int i = 0; i < 128; i++) {
        int fi = t + NTH * i;                  // 0..65535
        float wv = wvs[fi >> 9];               // 512 float4 per row
        float4 v = wbase[fi];
        v.x = __expf(v.x) * wv;
        v.y = __expf(v.y) * wv;
        v.z = __expf(v.z) * wv;
        v.w = __expf(v.w) * wv;
        wbase[fi] = v;
    }
}

// ===========================================================================
extern "C" void kernel_launch(void* const* d_in, const int* in_sizes, int n_in,
                              void* d_out, int out_size) {
    const float* Q = (const float*)d_in[0];
    const float* K = (const float*)d_in[1];
    const float* V = (const float*)d_in[2];
    float* out = (float*)d_out;

    cudaFuncSetAttribute(attn_mma, cudaFuncAttributeMaxDynamicSharedMemorySize, SMEM_TOTAL);

    prep_split<<<dim3((BB * SS * DD) / 256, 3), 256>>>(Q, K, V);
    attn_mma<<<BB * (SS / 128), NTH, SMEM_TOTAL>>>(out);
}